// round 16
// baseline (speedup 1.0000x reference)
#include <cuda_runtime.h>
#include <math.h>

// Problem constants
#define VOCAB 50000
#define EMB   300
#define HID   256
#define BATCH 128
#define T_H   32
#define T_B   512

typedef unsigned long long ULL;

// -------- scratch (static device allocations; no cudaMalloc anywhere) --------
__device__ float g_XG_h[(size_t)BATCH * T_H * 768];   // headline x-projections [B*T, 768]
__device__ float g_XG_b[(size_t)BATCH * T_B * 768];   // body x-projections
__device__ float g_out_h[(size_t)BATCH * T_H * HID];  // headline layer-0 outputs
__device__ float g_out_b[(size_t)BATCH * T_B * HID];  // body layer-0 outputs
__device__ float g_hcat [(size_t)BATCH * 512];        // [h_head | h_body] final states

// ---- packed f32x2 helpers (fp32-exact) ----
__device__ __forceinline__ void fma2(ULL& d, ULL a, ULL b) {
    asm("fma.rn.f32x2 %0, %1, %2, %0;" : "+l"(d) : "l"(a), "l"(b));
}
__device__ __forceinline__ ULL add2(ULL a, ULL b) {
    ULL d; asm("add.rn.f32x2 %0, %1, %2;" : "=l"(d) : "l"(a), "l"(b)); return d;
}
__device__ __forceinline__ ULL dup2(float x) {
    ULL r; asm("mov.b64 %0, {%1, %1};" : "=l"(r) : "f"(x)); return r;
}
__device__ __forceinline__ ULL packf2(float a, float b) {
    ULL r; asm("mov.b64 %0, {%1, %2};" : "=l"(r) : "f"(a), "f"(b)); return r;
}
__device__ __forceinline__ void unpack2(ULL v, float& a, float& b) {
    asm("mov.b64 {%0, %1}, %2;" : "=f"(a), "=f"(b) : "l"(v));
}

// ---- cluster / DSMEM helpers ----
__device__ __forceinline__ void cluster_sync_() {
    asm volatile("barrier.cluster.arrive.aligned;" ::: "memory");
    asm volatile("barrier.cluster.wait.aligned;" ::: "memory");
}
__device__ __forceinline__ unsigned s2u(const void* p) {
    return (unsigned)__cvta_generic_to_shared(p);
}
__device__ __forceinline__ unsigned mapa_sh(unsigned local, unsigned rank) {
    unsigned r;
    asm("mapa.shared::cluster.u32 %0, %1, %2;" : "=r"(r) : "r"(local), "r"(rank));
    return r;
}
__device__ __forceinline__ void st_dsmem_u64(unsigned addr, ULL v) {
    asm volatile("st.shared::cluster.u64 [%0], %1;" :: "r"(addr), "l"(v) : "memory");
}
__device__ __forceinline__ void st_dsmem_u32(unsigned addr, float v) {
    asm volatile("st.shared::cluster.u32 [%0], %1;" :: "r"(addr), "r"(__float_as_uint(v)) : "memory");
}

// ============================================================================
// Generic SGEMM (unchanged): C[M,N] = A[M,K] @ B[K,N] + bias, row-major.
// ============================================================================
template <bool GATHER>
__global__ __launch_bounds__(256)
void sgemm_kernel(const float* __restrict__ A, const int* __restrict__ ids, int lda,
                  const float* __restrict__ Bm, int ldb,
                  const float* __restrict__ bias,
                  float* __restrict__ C, int ldc, int coff,
                  int M, int N, int K)
{
    const int BM = 128, BN = 64, BK = 8;
    __shared__ float As[BK][BM];
    __shared__ float Bs[BK][BN];

    int nbn = N / BN;
    int bm = blockIdx.x / nbn;
    int bn = blockIdx.x % nbn;
    int tid = threadIdx.x;
    int tx = tid & 15;
    int ty = tid >> 4;

    float acc[8][4];
#pragma unroll
    for (int i = 0; i < 8; i++)
#pragma unroll
        for (int j = 0; j < 4; j++) acc[i][j] = 0.0f;

    int ar = tid >> 1;
    int ak = (tid & 1) * 4;
    int arow = bm * BM + ar;
    const float* arow_ptr;
    if (GATHER) arow_ptr = A + (size_t)ids[arow] * lda;
    else        arow_ptr = A + (size_t)arow * lda;

    int bkr = tid >> 5;
    int bc  = (tid & 31) * 2;
    const float* bptr = Bm + (size_t)bn * BN + bc;

    for (int k0 = 0; k0 < K; k0 += BK) {
        float4 av = make_float4(0.f, 0.f, 0.f, 0.f);
        if (k0 + ak < K) av = *(const float4*)(arow_ptr + k0 + ak);
        float2 bv = make_float2(0.f, 0.f);
        if (k0 + bkr < K) bv = *(const float2*)(bptr + (size_t)(k0 + bkr) * ldb);

        __syncthreads();
        As[ak + 0][ar] = av.x; As[ak + 1][ar] = av.y;
        As[ak + 2][ar] = av.z; As[ak + 3][ar] = av.w;
        Bs[bkr][bc] = bv.x; Bs[bkr][bc + 1] = bv.y;
        __syncthreads();

#pragma unroll
        for (int kk = 0; kk < BK; kk++) {
            float4 b4 = *(const float4*)&Bs[kk][tx * 4];
            float4 a0 = *(const float4*)&As[kk][ty * 8];
            float4 a1 = *(const float4*)&As[kk][ty * 8 + 4];
            float arr[8] = {a0.x, a0.y, a0.z, a0.w, a1.x, a1.y, a1.z, a1.w};
            float brr[4] = {b4.x, b4.y, b4.z, b4.w};
#pragma unroll
            for (int i = 0; i < 8; i++)
#pragma unroll
                for (int j = 0; j < 4; j++)
                    acc[i][j] += arr[i] * brr[j];
        }
    }

    float4 bb = *(const float4*)&bias[bn * BN + tx * 4];
    float bbr[4] = {bb.x, bb.y, bb.z, bb.w};
#pragma unroll
    for (int i = 0; i < 8; i++) {
        int row = bm * BM + ty * 8 + i;
        float4 o;
        o.x = acc[i][0] + bbr[0];
        o.y = acc[i][1] + bbr[1];
        o.z = acc[i][2] + bbr[2];
        o.w = acc[i][3] + bbr[3];
        *(float4*)(C + (size_t)row * ldc + coff + bn * BN + tx * 4) = o;
    }
}

// ============================================================================
// GRU scan, round 16: 4-CTA cluster, 8 batch rows, 4-way column split.
//   rank r: gate cols [128r,128r+128)  +  cand cols [64r,64r+64)
//   ranks 0,1 produce rh (r-gate halves); ranks 2,3 produce u.
//   Per-CTA weight working set = 192 KB -> mostly L1-resident (smem 56 KB).
//   rh/u/c broadcast to 3 peers via st.shared::cluster; ordering via the two
//   per-step cluster barriers (arrive=release / wait=acquire). u is
//   double-buffered (only cross-step racy buffer); rh/c structurally safe.
//   h is replicated in all 4 CTAs (update recomputed from identical inputs).
// Grid = 128 blocks (32 clusters of 4): [0,64) body, [64,128) head.
// ============================================================================
struct ScanArgs {
    const float* XG;
    const float* Wgh;   // [256,512] k-major h-part of gate weights
    const float* Wch;   // [256,256] k-major h-part of cand weights
    const int*   ids;
    float*       outs;
    float*       hfin;
    int          hoff;
    int          T;
};

__global__ void __cluster_dims__(4, 1, 1) __launch_bounds__(512)
gru_scan_c4(ScanArgs body, ScanArgs head)
{
    __shared__ ULL   PART[2048];       // gate [4][32][4][4] / cand [8][16][4][4]  16KB
    __shared__ float h_s [256 * 8];    // h[k][row], row minor                      8KB
    __shared__ float rh_s[256 * 8];    // r*h, same layout                          8KB
    __shared__ float u_s[2][8][256];   // u[buf][row][col], double-buffered        16KB
    __shared__ float c_s[8][256];      // cand[row][col]                            8KB
    __shared__ int   sv[8];

    const int bx = blockIdx.x;
    ScanArgs A = (bx < 64) ? body : head;
    const int rank = bx & 3;
    const int pgl  = (bx & 63) >> 2;
    const int b0   = pgl * 8;
    const int tid  = threadIdx.x;
    const int T    = A.T;

    for (int i = tid; i < 2048; i += 512) h_s[i] = 0.f;
    __syncthreads();

    const int cb  = rank << 7;   // gate col base (0/128/256/384)
    const int cbc = rank << 6;   // cand col base (0/64/128/192)

    // gate mainloop mapping: colquad x rowpair x 4 k-splits (64 k each)
    const int g_cq = tid & 31;
    const int g_rp = (tid >> 5) & 3;
    const int g_ks = tid >> 7;
    const float* __restrict__ wg = A.Wgh + (size_t)(g_ks * 64) * 512 + cb + g_cq * 4;

    // cand mainloop mapping: colquad x rowpair x 8 k-splits (32 k each)
    const int c_cq = tid & 15;
    const int c_rp = (tid >> 4) & 3;
    const int c_ks = tid >> 6;
    const float* __restrict__ wc = A.Wch + (size_t)(c_ks * 32) * 256 + cbc + c_cq * 4;

    // combine mappings
    const int gc_cp = tid & 63;        // colpair within own 128 gate cols
    const int gc_r  = tid >> 6;        // row 0..7
    const int cc_cp = tid & 31;        // colpair within own 64 cand cols (tid<256)
    const int cc_r  = tid >> 5;

    const unsigned rh_base = s2u(rh_s);
    const unsigned u_base  = s2u(u_s);
    const unsigned c_base  = s2u(c_s);

    cluster_sync_();   // all CTAs alive before any DSMEM traffic

    for (int t = 0; t < T; t++) {
        const int buf = t & 1;

        // ---- prefetch x-parts + validity ----
        const float2 xg2 = *(const float2*)(A.XG +
            (size_t)((b0 + gc_r) * T + t) * 768 + cb + 2 * gc_cp);
        float2 xc2 = make_float2(0.f, 0.f);
        if (tid < 256)
            xc2 = *(const float2*)(A.XG +
                (size_t)((b0 + cc_r) * T + t) * 768 + 512 + cbc + 2 * cc_cp);
        if (tid < 8) sv[tid] = A.ids[(b0 + tid) * T + t];

        // ---- gate mainloop: 4 cols x 2 rows over 64 k ----
        {
            ULL a0 = 0ull, a1 = 0ull, a2 = 0ull, a3 = 0ull; // 01_ra,23_ra,01_rb,23_rb
            const float* hp = h_s + (g_ks * 64) * 8 + 2 * g_rp;
#pragma unroll 16
            for (int kk = 0; kk < 64; kk++) {
                float4 w  = *(const float4*)(wg + (size_t)kk * 512);
                float2 h2 = *(const float2*)(hp + kk * 8);
                ULL w01 = packf2(w.x, w.y), w23 = packf2(w.z, w.w);
                ULL ha = dup2(h2.x), hb = dup2(h2.y);
                fma2(a0, w01, ha); fma2(a1, w23, ha);
                fma2(a2, w01, hb); fma2(a3, w23, hb);
            }
            ULL* dst = PART + ((size_t)(g_ks * 32 + g_cq) * 4 + g_rp) * 4;
            dst[0] = a0; dst[1] = a1; dst[2] = a2; dst[3] = a3;
        }
        __syncthreads();

        // ---- gate combine + sigmoid; ranks 0,1 -> rh; ranks 2,3 -> u ----
        {
            int cq  = gc_cp >> 1, rp = gc_r >> 1;
            int idx = (gc_cp & 1) + 2 * (gc_r & 1);
            ULL s = add2(add2(PART[((0 * 32 + cq) * 4 + rp) * 4 + idx],
                              PART[((1 * 32 + cq) * 4 + rp) * 4 + idx]),
                         add2(PART[((2 * 32 + cq) * 4 + rp) * 4 + idx],
                              PART[((3 * 32 + cq) * 4 + rp) * 4 + idx]));
            float s0, s1; unpack2(s, s0, s1);
            float g0 = 1.f / (1.f + expf(-(s0 + xg2.x)));
            float g1 = 1.f / (1.f + expf(-(s1 + xg2.y)));
            if (rank < 2) {
                int k0 = cb + 2 * gc_cp;                 // global k of first col
                float r0 = g0 * h_s[k0 * 8 + gc_r];
                float r1 = g1 * h_s[(k0 + 1) * 8 + gc_r];
                rh_s[k0 * 8 + gc_r]       = r0;
                rh_s[(k0 + 1) * 8 + gc_r] = r1;
                unsigned off0 = (unsigned)((k0 * 8 + gc_r) * 4);
                unsigned off1 = (unsigned)(((k0 + 1) * 8 + gc_r) * 4);
#pragma unroll
                for (int p = 0; p < 4; p++) if (p != rank) {
                    unsigned pb = mapa_sh(rh_base, (unsigned)p);
                    st_dsmem_u32(pb + off0, r0);
                    st_dsmem_u32(pb + off1, r1);
                }
            } else {
                int uc = (rank - 2) * 128 + 2 * gc_cp;   // u column 0..255
                ULL u2v = packf2(g0, g1);
                *(ULL*)&u_s[buf][gc_r][uc] = u2v;
                unsigned off = (unsigned)(((buf * 8 + gc_r) * 256 + uc) * 4);
#pragma unroll
                for (int p = 0; p < 4; p++) if (p != rank)
                    st_dsmem_u64(mapa_sh(u_base, (unsigned)p) + off, u2v);
            }
        }
        cluster_sync_();   // S1: rh visible everywhere (u en route, buffered)

        // ---- cand mainloop: 4 cols x 2 rows over 32 k ----
        {
            ULL a0 = 0ull, a1 = 0ull, a2 = 0ull, a3 = 0ull;
            const float* rp_ = rh_s + (c_ks * 32) * 8 + 2 * c_rp;
#pragma unroll 16
            for (int kk = 0; kk < 32; kk++) {
                float4 w  = *(const float4*)(wc + (size_t)kk * 256);
                float2 r2 = *(const float2*)(rp_ + kk * 8);
                ULL w01 = packf2(w.x, w.y), w23 = packf2(w.z, w.w);
                ULL ra = dup2(r2.x), rb = dup2(r2.y);
                fma2(a0, w01, ra); fma2(a1, w23, ra);
                fma2(a2, w01, rb); fma2(a3, w23, rb);
            }
            ULL* dst = PART + ((size_t)(c_ks * 16 + c_cq) * 4 + c_rp) * 4;
            dst[0] = a0; dst[1] = a1; dst[2] = a2; dst[3] = a3;
        }
        __syncthreads();

        // ---- cand combine + tanh (tid < 256) ----
        if (tid < 256) {
            int cq  = cc_cp >> 1, rp = cc_r >> 1;
            int idx = (cc_cp & 1) + 2 * (cc_r & 1);
            ULL s = add2(add2(add2(PART[((0 * 16 + cq) * 4 + rp) * 4 + idx],
                                   PART[((1 * 16 + cq) * 4 + rp) * 4 + idx]),
                              add2(PART[((2 * 16 + cq) * 4 + rp) * 4 + idx],
                                   PART[((3 * 16 + cq) * 4 + rp) * 4 + idx])),
                         add2(add2(PART[((4 * 16 + cq) * 4 + rp) * 4 + idx],
                                   PART[((5 * 16 + cq) * 4 + rp) * 4 + idx]),
                              add2(PART[((6 * 16 + cq) * 4 + rp) * 4 + idx],
                                   PART[((7 * 16 + cq) * 4 + rp) * 4 + idx])));
            float s0, s1; unpack2(s, s0, s1);
            float c0 = tanhf(s0 + xc2.x);
            float c1 = tanhf(s1 + xc2.y);
            int gc = cbc + 2 * cc_cp;
            ULL c2v = packf2(c0, c1);
            *(ULL*)&c_s[cc_r][gc] = c2v;
            unsigned off = (unsigned)((cc_r * 256 + gc) * 4);
#pragma unroll
            for (int p = 0; p < 4; p++) if (p != rank)
                st_dsmem_u64(mapa_sh(c_base, (unsigned)p) + off, c2v);
        }
        cluster_sync_();   // S2: u and c complete everywhere

        // ---- update (replicated in all 4 CTAs; identical inputs) ----
        if (tid < 256) {
            int col = tid;
            float hv[8];
            *(float4*)&hv[0] = *(const float4*)&h_s[col * 8];
            *(float4*)&hv[4] = *(const float4*)&h_s[col * 8 + 4];
            bool own = (col >> 6) == rank;
#pragma unroll
            for (int r = 0; r < 8; r++) {
                float u = u_s[buf][r][col];
                float c = c_s[r][col];
                float hn = u * hv[r] + (1.f - u) * c;
                bool v = sv[r] != 0;
                if (A.outs && own)
                    A.outs[(size_t)((b0 + r) * T + t) * 256 + col] = v ? hn : 0.f;
                hv[r] = v ? hn : hv[r];
            }
            *(float4*)&h_s[col * 8]     = *(const float4*)&hv[0];
            *(float4*)&h_s[col * 8 + 4] = *(const float4*)&hv[4];
        }
        __syncthreads();   // h ready for next gate mainloop
    }

    // ---- final hidden state (own 64-col slice) ----
    if (A.hfin && tid < 256) {
        int col = tid;
        if ((col >> 6) == rank) {
#pragma unroll
            for (int r = 0; r < 8; r++)
                A.hfin[(size_t)(b0 + r) * 512 + A.hoff + col] = h_s[col * 8 + r];
        }
    }
    cluster_sync_();   // no CTA exits while peers may still DSMEM-target it
}

// ============================================================================
// Final projection: out[128,4] = [h_head | h_body] @ W_pred + b_pred
// ============================================================================
__global__ void final_pred_kernel(const float* __restrict__ Wp,
                                  const float* __restrict__ bp,
                                  float* __restrict__ out)
{
    int b = threadIdx.x;
    float a0 = bp[0], a1 = bp[1], a2 = bp[2], a3 = bp[3];
    const float* h = g_hcat + (size_t)b * 512;
#pragma unroll 8
    for (int j = 0; j < 512; j++) {
        float hv = h[j];
        float4 w = *(const float4*)(Wp + j * 4);
        a0 += hv * w.x; a1 += hv * w.y; a2 += hv * w.z; a3 += hv * w.w;
    }
    *(float4*)(out + b * 4) = make_float4(a0, a1, a2, a3);
}

// ============================================================================
// Launch
// ============================================================================
extern "C" void kernel_launch(void* const* d_in, const int* in_sizes, int n_in,
                              void* d_out, int out_size)
{
    (void)n_in; (void)out_size;

    const int*   ids_h  = (const int*)d_in[0];
    const int*   ids_b  = (const int*)d_in[1];
    const float* emb    = (const float*)d_in[2];

    const float *hd0_Wg, *hd0_bg, *hd0_Wc, *hd0_bc;
    const float *hd1_Wg, *hd1_bg, *hd1_Wc, *hd1_bc;
    const float *bd0_Wg, *bd0_bg, *bd0_Wc, *bd0_bc;
    const float *bd1_Wg, *bd1_bg, *bd1_Wc, *bd1_bc;
    const float *W_pred, *b_pred;

    if (in_sizes[3] == (2 * HID) * 4 && in_sizes[4] == 4) {
        W_pred = (const float*)d_in[3];
        b_pred = (const float*)d_in[4];
        hd0_Wg = (const float*)d_in[5];  hd0_bg = (const float*)d_in[6];
        hd0_Wc = (const float*)d_in[7];  hd0_bc = (const float*)d_in[8];
        hd1_Wg = (const float*)d_in[9];  hd1_bg = (const float*)d_in[10];
        hd1_Wc = (const float*)d_in[11]; hd1_bc = (const float*)d_in[12];
        bd0_Wg = (const float*)d_in[13]; bd0_bg = (const float*)d_in[14];
        bd0_Wc = (const float*)d_in[15]; bd0_bc = (const float*)d_in[16];
        bd1_Wg = (const float*)d_in[17]; bd1_bg = (const float*)d_in[18];
        bd1_Wc = (const float*)d_in[19]; bd1_bc = (const float*)d_in[20];
    } else {
        hd0_Wg = (const float*)d_in[3];  hd0_bg = (const float*)d_in[4];
        hd0_Wc = (const float*)d_in[5];  hd0_bc = (const float*)d_in[6];
        hd1_Wg = (const float*)d_in[7];  hd1_bg = (const float*)d_in[8];
        hd1_Wc = (const float*)d_in[9];  hd1_bc = (const float*)d_in[10];
        bd0_Wg = (const float*)d_in[11]; bd0_bg = (const float*)d_in[12];
        bd0_Wc = (const float*)d_in[13]; bd0_bc = (const float*)d_in[14];
        bd1_Wg = (const float*)d_in[15]; bd1_bg = (const float*)d_in[16];
        bd1_Wc = (const float*)d_in[17]; bd1_bc = (const float*)d_in[18];
        W_pred = (const float*)d_in[19];
        b_pred = (const float*)d_in[20];
    }

    float* out = (float*)d_out;

    float *XG_h, *XG_b, *out_h, *out_b, *hcat;
    cudaGetSymbolAddress((void**)&XG_h, g_XG_h);
    cudaGetSymbolAddress((void**)&XG_b, g_XG_b);
    cudaGetSymbolAddress((void**)&out_h, g_out_h);
    cudaGetSymbolAddress((void**)&out_b, g_out_b);
    cudaGetSymbolAddress((void**)&hcat, g_hcat);

    const int Mh = BATCH * T_H;
    const int Mb = BATCH * T_B;

    // ---- Layer-0 x-projections (embedding gather fused) ----
    sgemm_kernel<true><<<(Mh / 128) * (512 / 64), 256>>>(
        emb, ids_h, EMB, hd0_Wg, 512, hd0_bg, XG_h, 768, 0,   Mh, 512, EMB);
    sgemm_kernel<true><<<(Mh / 128) * (256 / 64), 256>>>(
        emb, ids_h, EMB, hd0_Wc, 256, hd0_bc, XG_h, 768, 512, Mh, 256, EMB);
    sgemm_kernel<true><<<(Mb / 128) * (512 / 64), 256>>>(
        emb, ids_b, EMB, bd0_Wg, 512, bd0_bg, XG_b, 768, 0,   Mb, 512, EMB);
    sgemm_kernel<true><<<(Mb / 128) * (256 / 64), 256>>>(
        emb, ids_b, EMB, bd0_Wc, 256, bd0_bc, XG_b, 768, 512, Mb, 256, EMB);

    // ---- Layer-0 scan ----
    {
        ScanArgs body = { XG_b, bd0_Wg + (size_t)EMB * 512, bd0_Wc + (size_t)EMB * 256,
                          ids_b, out_b, nullptr, 0, T_B };
        ScanArgs head = { XG_h, hd0_Wg + (size_t)EMB * 512, hd0_Wc + (size_t)EMB * 256,
                          ids_h, out_h, nullptr, 0, T_H };
        gru_scan_c4<<<128, 512>>>(body, head);
    }

    // ---- Layer-1 x-projections ----
    sgemm_kernel<false><<<(Mh / 128) * (512 / 64), 256>>>(
        out_h, nullptr, HID, hd1_Wg, 512, hd1_bg, XG_h, 768, 0,   Mh, 512, HID);
    sgemm_kernel<false><<<(Mh / 128) * (256 / 64), 256>>>(
        out_h, nullptr, HID, hd1_Wc, 256, hd1_bc, XG_h, 768, 512, Mh, 256, HID);
    sgemm_kernel<false><<<(Mb / 128) * (512 / 64), 256>>>(
        out_b, nullptr, HID, bd1_Wg, 512, bd1_bg, XG_b, 768, 0,   Mb, 512, HID);
    sgemm_kernel<false><<<(Mb / 128) * (256 / 64), 256>>>(
        out_b, nullptr, HID, bd1_Wc, 256, bd1_bc, XG_b, 768, 512, Mb, 256, HID);

    // ---- Layer-1 scan ----
    {
        ScanArgs body = { XG_b, bd1_Wg + (size_t)HID * 512, bd1_Wc + (size_t)HID * 256,
                          ids_b, nullptr, hcat, 256, T_B };
        ScanArgs head = { XG_h, hd1_Wg + (size_t)HID * 512, hd1_Wc + (size_t)HID * 256,
                          ids_h, nullptr, hcat, 0, T_H };
        gru_scan_c4<<<128, 512>>>(body, head);
    }

    // ---- Final projection ----
    final_pred_kernel<<<1, 128>>>(W_pred, b_pred, out);
}

// round 17
// speedup vs baseline: 1.5160x; 1.5160x over previous
#include <cuda_runtime.h>
#include <math.h>

// Problem constants
#define VOCAB 50000
#define EMB   300
#define HID   256
#define BATCH 128
#define T_H   32
#define T_B   512

typedef unsigned long long ULL;

// -------- scratch (static device allocations; no cudaMalloc anywhere) --------
__device__ float g_XG_h[(size_t)BATCH * T_H * 768];   // headline x-projections [B*T, 768]
__device__ float g_XG_b[(size_t)BATCH * T_B * 768];   // body x-projections
__device__ float g_out_h[(size_t)BATCH * T_H * HID];  // headline layer-0 outputs
__device__ float g_out_b[(size_t)BATCH * T_B * HID];  // body layer-0 outputs
__device__ float g_hcat [(size_t)BATCH * 512];        // [h_head | h_body] final states

// ---- packed f32x2 helpers (fp32-exact) ----
__device__ __forceinline__ void fma2(ULL& d, ULL a, ULL b) {
    asm("fma.rn.f32x2 %0, %1, %2, %0;" : "+l"(d) : "l"(a), "l"(b));
}
__device__ __forceinline__ ULL add2(ULL a, ULL b) {
    ULL d; asm("add.rn.f32x2 %0, %1, %2;" : "=l"(d) : "l"(a), "l"(b)); return d;
}
__device__ __forceinline__ ULL dup2(float x) {
    ULL r; asm("mov.b64 %0, {%1, %1};" : "=l"(r) : "f"(x)); return r;
}
__device__ __forceinline__ ULL packf2(float a, float b) {
    ULL r; asm("mov.b64 %0, {%1, %2};" : "=l"(r) : "f"(a), "f"(b)); return r;
}
__device__ __forceinline__ void unpack2(ULL v, float& a, float& b) {
    asm("mov.b64 {%0, %1}, %2;" : "=f"(a), "=f"(b) : "l"(v));
}

// ---- cluster / DSMEM helpers ----
__device__ __forceinline__ void cluster_sync_() {
    asm volatile("barrier.cluster.arrive.aligned;" ::: "memory");
    asm volatile("barrier.cluster.wait.aligned;" ::: "memory");
}
__device__ __forceinline__ unsigned s2u(const void* p) {
    return (unsigned)__cvta_generic_to_shared(p);
}
__device__ __forceinline__ unsigned mapa_sh(unsigned local, unsigned rank) {
    unsigned r;
    asm("mapa.shared::cluster.u32 %0, %1, %2;" : "=r"(r) : "r"(local), "r"(rank));
    return r;
}
__device__ __forceinline__ void st_dsmem_u64(unsigned addr, ULL v) {
    asm volatile("st.shared::cluster.u64 [%0], %1;" :: "r"(addr), "l"(v) : "memory");
}

// ============================================================================
// Generic SGEMM (unchanged): C[M,N] = A[M,K] @ B[K,N] + bias, row-major.
// ============================================================================
template <bool GATHER>
__global__ __launch_bounds__(256)
void sgemm_kernel(const float* __restrict__ A, const int* __restrict__ ids, int lda,
                  const float* __restrict__ Bm, int ldb,
                  const float* __restrict__ bias,
                  float* __restrict__ C, int ldc, int coff,
                  int M, int N, int K)
{
    const int BM = 128, BN = 64, BK = 8;
    __shared__ float As[BK][BM];
    __shared__ float Bs[BK][BN];

    int nbn = N / BN;
    int bm = blockIdx.x / nbn;
    int bn = blockIdx.x % nbn;
    int tid = threadIdx.x;
    int tx = tid & 15;
    int ty = tid >> 4;

    float acc[8][4];
#pragma unroll
    for (int i = 0; i < 8; i++)
#pragma unroll
        for (int j = 0; j < 4; j++) acc[i][j] = 0.0f;

    int ar = tid >> 1;
    int ak = (tid & 1) * 4;
    int arow = bm * BM + ar;
    const float* arow_ptr;
    if (GATHER) arow_ptr = A + (size_t)ids[arow] * lda;
    else        arow_ptr = A + (size_t)arow * lda;

    int bkr = tid >> 5;
    int bc  = (tid & 31) * 2;
    const float* bptr = Bm + (size_t)bn * BN + bc;

    for (int k0 = 0; k0 < K; k0 += BK) {
        float4 av = make_float4(0.f, 0.f, 0.f, 0.f);
        if (k0 + ak < K) av = *(const float4*)(arow_ptr + k0 + ak);
        float2 bv = make_float2(0.f, 0.f);
        if (k0 + bkr < K) bv = *(const float2*)(bptr + (size_t)(k0 + bkr) * ldb);

        __syncthreads();
        As[ak + 0][ar] = av.x; As[ak + 1][ar] = av.y;
        As[ak + 2][ar] = av.z; As[ak + 3][ar] = av.w;
        Bs[bkr][bc] = bv.x; Bs[bkr][bc + 1] = bv.y;
        __syncthreads();

#pragma unroll
        for (int kk = 0; kk < BK; kk++) {
            float4 b4 = *(const float4*)&Bs[kk][tx * 4];
            float4 a0 = *(const float4*)&As[kk][ty * 8];
            float4 a1 = *(const float4*)&As[kk][ty * 8 + 4];
            float arr[8] = {a0.x, a0.y, a0.z, a0.w, a1.x, a1.y, a1.z, a1.w};
            float brr[4] = {b4.x, b4.y, b4.z, b4.w};
#pragma unroll
            for (int i = 0; i < 8; i++)
#pragma unroll
                for (int j = 0; j < 4; j++)
                    acc[i][j] += arr[i] * brr[j];
        }
    }

    float4 bb = *(const float4*)&bias[bn * BN + tx * 4];
    float bbr[4] = {bb.x, bb.y, bb.z, bb.w};
#pragma unroll
    for (int i = 0; i < 8; i++) {
        int row = bm * BM + ty * 8 + i;
        float4 o;
        o.x = acc[i][0] + bbr[0];
        o.y = acc[i][1] + bbr[1];
        o.z = acc[i][2] + bbr[2];
        o.w = acc[i][3] + bbr[3];
        *(float4*)(C + (size_t)row * ldc + coff + bn * BN + tx * 4) = o;
    }
}

// ============================================================================
// GRU scan, round 17: cluster(2), 1024 threads (R15 core), re-partitioned so
// almost nothing crosses the CTA boundary.
//   rank r owns hidden cols [128r,128r+128):
//     gate phase: computes r-gates for its k-half AND u-gates for its h-half
//                 (gate cols {128r..128r+128} U {256+128r..+128}) -> rh, u LOCAL
//     cand phase: k-split -- uses local rh half against ALL 256 cand cols;
//                 only 2 KB of partials cross via DSMEM
//     update: own h half; 2 KB h-half exchanged via DSMEM
// Two cluster syncs per step (S_a after partial send, S_b after h send), but
// gate ML -> combine -> cand ML run with no cross-CTA wait.
// Grid = 128 blocks (64 clusters): [0,64) body, [64,128) head.
// ============================================================================
struct ScanArgs {
    const float* XG;
    const float* Wgh;   // [256,512] k-major h-part of gate weights
    const float* Wch;   // [256,256] k-major h-part of cand weights
    const int*   ids;
    float*       outs;
    float*       hfin;
    int          hoff;
    int          T;
};

__global__ void __cluster_dims__(2, 1, 1) __launch_bounds__(1024)
gru_scan_c2v2(ScanArgs body, ScanArgs head)
{
    __shared__ ULL sh_part[4096];      // gate [8][256][2] / cand [4][256][2]  32KB
    __shared__ ULL h_pk [256][2];      // full h, packed row-pairs              4KB
    __shared__ ULL rh_pk[128][2];      // r*h for OWN k-half (local only)       2KB
    __shared__ ULL u_pk [128][2];      // u for own h-half (local only)         2KB
    __shared__ ULL red_loc[128][2];    // own-col cand partial (local k-half)   2KB
    __shared__ ULL pred  [128][2];     // peer's cand partial for our cols      2KB
    __shared__ int sv[4];

    const int bx = blockIdx.x;
    ScanArgs A = (bx < 64) ? body : head;
    const int rank = bx & 1;
    const unsigned peer = 1u - (unsigned)rank;
    const int pgl = (bx & 63) >> 1;
    const int b0  = pgl * 4;
    const int tid = threadIdx.x;
    const int T = A.T;

    if (tid < 512) ((ULL*)h_pk)[tid] = 0ull;
    __syncthreads();

    // ---- gate mainloop mapping: 8 k-splits (32 k) x 128 owners (2 cols) ----
    const int ks = tid >> 7;            // 0..7
    const int ow = tid & 127;
    // owner's 2 gate columns: ow<64 -> r-chunk, ow>=64 -> u-chunk
    const int gcol = (ow < 64) ? (128 * rank + 2 * ow)
                               : (256 + 128 * rank + 2 * (ow - 64));
    const float* __restrict__ wg = A.Wgh + (size_t)(ks * 32) * 512 + gcol;

    // ---- cand mainloop mapping: 4 k-splits (32 k, own half) x 256 owners ----
    const int oc  = tid & 255;          // cand col 0..255 (all cols)
    const int cks = tid >> 8;           // 0..3
    const float* __restrict__ wc =
        A.Wch + (size_t)(128 * rank + cks * 32) * 256 + oc;

    // ---- combine / reduce mapping (tid < 512): local col c, rowpair rp ----
    const int gc_c  = tid >> 1;         // 0..255 local gate col
    const int gc_rp = tid & 1;
    const int gcc = (gc_c < 128) ? (128 * rank + gc_c)
                                 : (256 + 128 * rank + (gc_c - 128));

    // ---- finalize/update mapping (tid < 256): own col fo, rowpair frp ----
    const int fo  = tid >> 1;           // 0..127
    const int frp = tid & 1;
    const int gco = 128 * rank + fo;    // global hidden col

    // peer DSMEM bases (hoisted)
    const unsigned pred_peer = mapa_sh(s2u(pred), peer);
    const unsigned h_peer    = mapa_sh(s2u(h_pk), peer);

    cluster_sync_();   // both CTAs alive before any DSMEM traffic

    for (int t = 0; t < T; t++) {
        // ---- prefetch x-parts + validity ----
        float xg0 = 0.f, xg1 = 0.f;
        if (tid < 512) {
            xg0 = A.XG[(size_t)((b0 + 2 * gc_rp)     * T + t) * 768 + gcc];
            xg1 = A.XG[(size_t)((b0 + 2 * gc_rp + 1) * T + t) * 768 + gcc];
        }
        float xc0 = 0.f, xc1 = 0.f;
        if (tid < 256) {
            xc0 = A.XG[(size_t)((b0 + 2 * frp)     * T + t) * 768 + 512 + gco];
            xc1 = A.XG[(size_t)((b0 + 2 * frp + 1) * T + t) * 768 + 512 + gco];
        }
        if (tid < 4) sv[tid] = A.ids[(b0 + tid) * T + t];

        // ---- gate mainloop: 2 cols x 2 rowpairs over 32 k (full h) ----
        {
            ULL a00 = 0ull, a01 = 0ull, a10 = 0ull, a11 = 0ull;
#pragma unroll 16
            for (int kk = 0; kk < 32; kk++) {
                ULL w2 = *(const ULL*)(wg + (size_t)kk * 512);
                ULL hp0 = h_pk[ks * 32 + kk][0];
                ULL hp1 = h_pk[ks * 32 + kk][1];
                float w0f, w1f; unpack2(w2, w0f, w1f);
                ULL w0 = dup2(w0f), w1 = dup2(w1f);
                fma2(a00, w0, hp0); fma2(a01, w0, hp1);
                fma2(a10, w1, hp0); fma2(a11, w1, hp1);
            }
            // local gate col index: 2*ow, 2*ow+1
            ULL* dst = sh_part + (size_t)(ks * 256 + 2 * ow) * 2;
            dst[0] = a00; dst[1] = a01; dst[2] = a10; dst[3] = a11;
        }
        __syncthreads();

        // ---- gate combine + sigmoid (tid<512): rh and u both LOCAL ----
        if (tid < 512) {
            ULL s = add2(add2(add2(sh_part[(0 * 256 + gc_c) * 2 + gc_rp],
                                   sh_part[(1 * 256 + gc_c) * 2 + gc_rp]),
                              add2(sh_part[(2 * 256 + gc_c) * 2 + gc_rp],
                                   sh_part[(3 * 256 + gc_c) * 2 + gc_rp])),
                         add2(add2(sh_part[(4 * 256 + gc_c) * 2 + gc_rp],
                                   sh_part[(5 * 256 + gc_c) * 2 + gc_rp]),
                              add2(sh_part[(6 * 256 + gc_c) * 2 + gc_rp],
                                   sh_part[(7 * 256 + gc_c) * 2 + gc_rp])));
            float s0, s1; unpack2(s, s0, s1);
            float g0 = 1.f / (1.f + expf(-(s0 + xg0)));
            float g1 = 1.f / (1.f + expf(-(s1 + xg1)));
            if (gc_c < 128) {              // r gate for own k = gcc
                float h0, h1; unpack2(h_pk[gcc][gc_rp], h0, h1);
                rh_pk[gc_c][gc_rp] = packf2(g0 * h0, g1 * h1);
            } else {                       // u gate for own hidden col
                u_pk[gc_c - 128][gc_rp] = packf2(g0, g1);
            }
        }
        __syncthreads();

        // ---- cand mainloop: 1 col x 2 rowpairs over own 128 k (4 splits) ----
        {
            ULL c0a = 0ull, c1a = 0ull;
#pragma unroll 16
            for (int kk = 0; kk < 32; kk++) {
                float w = wc[(size_t)kk * 256];
                ULL wd = dup2(w);
                fma2(c0a, wd, rh_pk[cks * 32 + kk][0]);
                fma2(c1a, wd, rh_pk[cks * 32 + kk][1]);
            }
            sh_part[(cks * 256 + oc) * 2 + 0] = c0a;
            sh_part[(cks * 256 + oc) * 2 + 1] = c1a;
        }
        __syncthreads();

        // ---- reduce k-splits; keep own cols, send peer cols (tid<512) ----
        if (tid < 512) {
            int c = gc_c, rp = gc_rp;
            ULL r4 = add2(add2(sh_part[(0 * 256 + c) * 2 + rp],
                               sh_part[(1 * 256 + c) * 2 + rp]),
                          add2(sh_part[(2 * 256 + c) * 2 + rp],
                               sh_part[(3 * 256 + c) * 2 + rp]));
            if ((c >> 7) == rank)
                red_loc[c & 127][rp] = r4;
            else
                st_dsmem_u64(pred_peer + (unsigned)((c & 127) * 2 + rp) * 8u, r4);
        }
        cluster_sync_();   // S_a: peer partials landed in pred

        // ---- finalize + update own h half (tid<256); send h half to peer ----
        if (tid < 256) {
            ULL s = add2(red_loc[fo][frp], pred[fo][frp]);
            float s0, s1; unpack2(s, s0, s1);
            float c0 = tanhf(s0 + xc0);
            float c1 = tanhf(s1 + xc1);
            float u0, u1; unpack2(u_pk[fo][frp], u0, u1);
            float h0, h1; unpack2(h_pk[gco][frp], h0, h1);
            float hn0 = u0 * h0 + (1.f - u0) * c0;
            float hn1 = u1 * h1 + (1.f - u1) * c1;
            bool v0 = sv[2 * frp] != 0, v1 = sv[2 * frp + 1] != 0;
            ULL hnew = packf2(v0 ? hn0 : h0, v1 ? hn1 : h1);
            h_pk[gco][frp] = hnew;
            st_dsmem_u64(h_peer + (unsigned)(gco * 2 + frp) * 8u, hnew);
            if (A.outs) {
                A.outs[(size_t)((b0 + 2 * frp)     * T + t) * 256 + gco] = v0 ? hn0 : 0.f;
                A.outs[(size_t)((b0 + 2 * frp + 1) * T + t) * 256 + gco] = v1 ? hn1 : 0.f;
            }
        }
        cluster_sync_();   // S_b: full h visible in both CTAs for next step
    }

    // ---- final hidden state (own col half) ----
    if (A.hfin && tid < 256) {
        float k0, k1; unpack2(h_pk[gco][frp], k0, k1);
        A.hfin[(size_t)(b0 + 2 * frp)     * 512 + A.hoff + gco] = k0;
        A.hfin[(size_t)(b0 + 2 * frp + 1) * 512 + A.hoff + gco] = k1;
    }
    cluster_sync_();   // no CTA exits while peer may still DSMEM-target it
}

// ============================================================================
// Final projection: out[128,4] = [h_head | h_body] @ W_pred + b_pred
// ============================================================================
__global__ void final_pred_kernel(const float* __restrict__ Wp,
                                  const float* __restrict__ bp,
                                  float* __restrict__ out)
{
    int b = threadIdx.x;
    float a0 = bp[0], a1 = bp[1], a2 = bp[2], a3 = bp[3];
    const float* h = g_hcat + (size_t)b * 512;
#pragma unroll 8
    for (int j = 0; j < 512; j++) {
        float hv = h[j];
        float4 w = *(const float4*)(Wp + j * 4);
        a0 += hv * w.x; a1 += hv * w.y; a2 += hv * w.z; a3 += hv * w.w;
    }
    *(float4*)(out + b * 4) = make_float4(a0, a1, a2, a3);
}

// ============================================================================
// Launch
// ============================================================================
extern "C" void kernel_launch(void* const* d_in, const int* in_sizes, int n_in,
                              void* d_out, int out_size)
{
    (void)n_in; (void)out_size;

    const int*   ids_h  = (const int*)d_in[0];
    const int*   ids_b  = (const int*)d_in[1];
    const float* emb    = (const float*)d_in[2];

    const float *hd0_Wg, *hd0_bg, *hd0_Wc, *hd0_bc;
    const float *hd1_Wg, *hd1_bg, *hd1_Wc, *hd1_bc;
    const float *bd0_Wg, *bd0_bg, *bd0_Wc, *bd0_bc;
    const float *bd1_Wg, *bd1_bg, *bd1_Wc, *bd1_bc;
    const float *W_pred, *b_pred;

    if (in_sizes[3] == (2 * HID) * 4 && in_sizes[4] == 4) {
        W_pred = (const float*)d_in[3];
        b_pred = (const float*)d_in[4];
        hd0_Wg = (const float*)d_in[5];  hd0_bg = (const float*)d_in[6];
        hd0_Wc = (const float*)d_in[7];  hd0_bc = (const float*)d_in[8];
        hd1_Wg = (const float*)d_in[9];  hd1_bg = (const float*)d_in[10];
        hd1_Wc = (const float*)d_in[11]; hd1_bc = (const float*)d_in[12];
        bd0_Wg = (const float*)d_in[13]; bd0_bg = (const float*)d_in[14];
        bd0_Wc = (const float*)d_in[15]; bd0_bc = (const float*)d_in[16];
        bd1_Wg = (const float*)d_in[17]; bd1_bg = (const float*)d_in[18];
        bd1_Wc = (const float*)d_in[19]; bd1_bc = (const float*)d_in[20];
    } else {
        hd0_Wg = (const float*)d_in[3];  hd0_bg = (const float*)d_in[4];
        hd0_Wc = (const float*)d_in[5];  hd0_bc = (const float*)d_in[6];
        hd1_Wg = (const float*)d_in[7];  hd1_bg = (const float*)d_in[8];
        hd1_Wc = (const float*)d_in[9];  hd1_bc = (const float*)d_in[10];
        bd0_Wg = (const float*)d_in[11]; bd0_bg = (const float*)d_in[12];
        bd0_Wc = (const float*)d_in[13]; bd0_bc = (const float*)d_in[14];
        bd1_Wg = (const float*)d_in[15]; bd1_bg = (const float*)d_in[16];
        bd1_Wc = (const float*)d_in[17]; bd1_bc = (const float*)d_in[18];
        W_pred = (const float*)d_in[19];
        b_pred = (const float*)d_in[20];
    }

    float* out = (float*)d_out;

    float *XG_h, *XG_b, *out_h, *out_b, *hcat;
    cudaGetSymbolAddress((void**)&XG_h, g_XG_h);
    cudaGetSymbolAddress((void**)&XG_b, g_XG_b);
    cudaGetSymbolAddress((void**)&out_h, g_out_h);
    cudaGetSymbolAddress((void**)&out_b, g_out_b);
    cudaGetSymbolAddress((void**)&hcat, g_hcat);

    const int Mh = BATCH * T_H;
    const int Mb = BATCH * T_B;

    // ---- Layer-0 x-projections (embedding gather fused) ----
    sgemm_kernel<true><<<(Mh / 128) * (512 / 64), 256>>>(
        emb, ids_h, EMB, hd0_Wg, 512, hd0_bg, XG_h, 768, 0,   Mh, 512, EMB);
    sgemm_kernel<true><<<(Mh / 128) * (256 / 64), 256>>>(
        emb, ids_h, EMB, hd0_Wc, 256, hd0_bc, XG_h, 768, 512, Mh, 256, EMB);
    sgemm_kernel<true><<<(Mb / 128) * (512 / 64), 256>>>(
        emb, ids_b, EMB, bd0_Wg, 512, bd0_bg, XG_b, 768, 0,   Mb, 512, EMB);
    sgemm_kernel<true><<<(Mb / 128) * (256 / 64), 256>>>(
        emb, ids_b, EMB, bd0_Wc, 256, bd0_bc, XG_b, 768, 512, Mb, 256, EMB);

    // ---- Layer-0 scan ----
    {
        ScanArgs body = { XG_b, bd0_Wg + (size_t)EMB * 512, bd0_Wc + (size_t)EMB * 256,
                          ids_b, out_b, nullptr, 0, T_B };
        ScanArgs head = { XG_h, hd0_Wg + (size_t)EMB * 512, hd0_Wc + (size_t)EMB * 256,
                          ids_h, out_h, nullptr, 0, T_H };
        gru_scan_c2v2<<<128, 1024>>>(body, head);
    }

    // ---- Layer-1 x-projections ----
    sgemm_kernel<false><<<(Mh / 128) * (512 / 64), 256>>>(
        out_h, nullptr, HID, hd1_Wg, 512, hd1_bg, XG_h, 768, 0,   Mh, 512, HID);
    sgemm_kernel<false><<<(Mh / 128) * (256 / 64), 256>>>(
        out_h, nullptr, HID, hd1_Wc, 256, hd1_bc, XG_h, 768, 512, Mh, 256, HID);
    sgemm_kernel<false><<<(Mb / 128) * (512 / 64), 256>>>(
        out_b, nullptr, HID, bd1_Wg, 512, bd1_bg, XG_b, 768, 0,   Mb, 512, HID);
    sgemm_kernel<false><<<(Mb / 128) * (256 / 64), 256>>>(
        out_b, nullptr, HID, bd1_Wc, 256, bd1_bc, XG_b, 768, 512, Mb, 256, HID);

    // ---- Layer-1 scan ----
    {
        ScanArgs body = { XG_b, bd1_Wg + (size_t)HID * 512, bd1_Wc + (size_t)HID * 256,
                          ids_b, nullptr, hcat, 256, T_B };
        ScanArgs head = { XG_h, hd1_Wg + (size_t)HID * 512, hd1_Wc + (size_t)HID * 256,
                          ids_h, nullptr, hcat, 0, T_H };
        gru_scan_c2v2<<<128, 1024>>>(body, head);
    }

    // ---- Final projection ----
    final_pred_kernel<<<1, 128>>>(W_pred, b_pred, out);
}